// round 16
// baseline (speedup 1.0000x reference)
#include <cuda_runtime.h>
#include <cuda_bf16.h>
#include <cuda_fp16.h>
#include <math.h>
#include <stdint.h>

// Problem constants
#define B_  2
#define S_  4096
#define D_  2048
#define H_  16
#define HD_ 128
#define MROWS (B_ * S_)   // 8192

// Scratch in __device__ globals (allocation-guard-safe)
__device__ float g_q [(size_t)MROWS * D_];
__device__ float g_k [(size_t)MROWS * D_];
__device__ float g_v [(size_t)MROWS * D_];
__device__ float g_ao[(size_t)MROWS * D_];
__device__ __half g_qh[(size_t)MROWS * D_];
__device__ __half g_kh[(size_t)MROWS * D_];
__device__ __half g_vh[(size_t)MROWS * D_];
__device__ __nv_bfloat16 g_xh [(size_t)MROWS * D_];
__device__ __nv_bfloat16 g_xl [(size_t)MROWS * D_];
__device__ __nv_bfloat16 g_aoh[(size_t)MROWS * D_];
__device__ __nv_bfloat16 g_aol[(size_t)MROWS * D_];
__device__ __nv_bfloat16 g_wqh[(size_t)D_ * D_];
__device__ __nv_bfloat16 g_wql[(size_t)D_ * D_];
__device__ __nv_bfloat16 g_wkh[(size_t)D_ * D_];
__device__ __nv_bfloat16 g_wkl[(size_t)D_ * D_];
__device__ __nv_bfloat16 g_wvh[(size_t)D_ * D_];
__device__ __nv_bfloat16 g_wvl[(size_t)D_ * D_];
__device__ __nv_bfloat16 g_woh[(size_t)D_ * D_];
__device__ __nv_bfloat16 g_wol[(size_t)D_ * D_];

// ---------------------------------------------------------------------------
// helpers
// ---------------------------------------------------------------------------
__device__ __forceinline__ void mma_bf16(float* c, const uint32_t* a, const uint32_t* b) {
    asm volatile(
        "mma.sync.aligned.m16n8k16.row.col.f32.bf16.bf16.f32 "
        "{%0,%1,%2,%3}, {%4,%5,%6,%7}, {%8,%9}, {%0,%1,%2,%3};\n"
        : "+f"(c[0]), "+f"(c[1]), "+f"(c[2]), "+f"(c[3])
        : "r"(a[0]), "r"(a[1]), "r"(a[2]), "r"(a[3]), "r"(b[0]), "r"(b[1]));
}

__device__ __forceinline__ void mma_fp16(float* c, const uint32_t* a, const uint32_t* b) {
    asm volatile(
        "mma.sync.aligned.m16n8k16.row.col.f32.f16.f16.f32 "
        "{%0,%1,%2,%3}, {%4,%5,%6,%7}, {%8,%9}, {%0,%1,%2,%3};\n"
        : "+f"(c[0]), "+f"(c[1]), "+f"(c[2]), "+f"(c[3])
        : "r"(a[0]), "r"(a[1]), "r"(a[2]), "r"(a[3]), "r"(b[0]), "r"(b[1]));
}

__device__ __forceinline__ uint32_t packbf(float a, float b) {
    __nv_bfloat162 t = __floats2bfloat162_rn(a, b);
    return *(uint32_t*)&t;
}

__device__ __forceinline__ uint32_t packhf(float a, float b) {
    __half2 t = __floats2half2_rn(a, b);
    return *(uint32_t*)&t;
}

__device__ __forceinline__ uint32_t smem_u32(const void* p) {
    uint32_t a;
    asm("{ .reg .u64 t; cvta.to.shared.u64 t, %1; cvt.u32.u64 %0, t; }" : "=r"(a) : "l"(p));
    return a;
}

__device__ __forceinline__ void ldsm_x4(uint32_t* r, uint32_t addr) {
    asm volatile("ldmatrix.sync.aligned.m8n8.x4.shared.b16 {%0,%1,%2,%3}, [%4];"
                 : "=r"(r[0]), "=r"(r[1]), "=r"(r[2]), "=r"(r[3]) : "r"(addr));
}

__device__ __forceinline__ void ldsm_x4_t(uint32_t* r, uint32_t addr) {
    asm volatile("ldmatrix.sync.aligned.m8n8.x4.trans.shared.b16 {%0,%1,%2,%3}, [%4];"
                 : "=r"(r[0]), "=r"(r[1]), "=r"(r[2]), "=r"(r[3]) : "r"(addr));
}

#define CP_ASYNC16(dst, src) \
    asm volatile("cp.async.cg.shared.global [%0], [%1], 16;" \
                 :: "r"((uint32_t)(dst)), "l"(src) : "memory")
#define CP_COMMIT() asm volatile("cp.async.commit_group;" ::: "memory")
#define CP_WAIT(n)  asm volatile("cp.async.wait_group %0;" :: "n"(n) : "memory")

// ---------------------------------------------------------------------------
// Prep: split fp32 array into bf16 hi/lo arrays
// ---------------------------------------------------------------------------
__global__ void __launch_bounds__(256) split_bf(const float* __restrict__ in,
                                               __nv_bfloat16* __restrict__ hi,
                                               __nv_bfloat16* __restrict__ lo,
                                               int n4)
{
    int i = blockIdx.x * 256 + threadIdx.x;
    if (i >= n4) return;
    float4 v = ((const float4*)in)[i];
    float hx = __bfloat162float(__float2bfloat16(v.x));
    float hy = __bfloat162float(__float2bfloat16(v.y));
    float hz = __bfloat162float(__float2bfloat16(v.z));
    float hw = __bfloat162float(__float2bfloat16(v.w));
    ((uint2*)hi)[i] = make_uint2(packbf(hx, hy), packbf(hz, hw));
    ((uint2*)lo)[i] = make_uint2(packbf(v.x - hx, v.y - hy), packbf(v.z - hz, v.w - hw));
}

// ---------------------------------------------------------------------------
// 3-pass split-bf16 GEMM, operands pre-split in gmem (UNCHANGED from R15)
// ---------------------------------------------------------------------------
#define LDTW 20
#define GSTAGE (128 * LDTW)
#define GEMM_SMEM_WORDS (8 * GSTAGE)   // 81920 B

__global__ void __launch_bounds__(256, 1) tbgemm3p_nt(const __nv_bfloat16* __restrict__ Ahg,
                                                      const __nv_bfloat16* __restrict__ Alg,
                                                      const __nv_bfloat16* __restrict__ Bhg,
                                                      const __nv_bfloat16* __restrict__ Blg,
                                                      float* __restrict__ C,
                                                      int M, int N, int K)
{
    extern __shared__ uint32_t sg[];
    uint32_t* Ah = sg;
    uint32_t* Al = Ah + 2 * GSTAGE;
    uint32_t* Bh = Al + 2 * GSTAGE;
    uint32_t* Bl = Bh + 2 * GSTAGE;

    const uint32_t* Ahw = (const uint32_t*)Ahg;
    const uint32_t* Alw = (const uint32_t*)Alg;
    const uint32_t* Bhw = (const uint32_t*)Bhg;
    const uint32_t* Blw = (const uint32_t*)Blg;
    const int Kw = K >> 1;

    const int tid    = threadIdx.x;
    const int warp   = tid >> 5;
    const int lane   = tid & 31;
    const int warp_m = warp >> 2;
    const int warp_n = warp & 3;
    const int g      = lane >> 2;
    const int tig    = lane & 3;

    const int bm = blockIdx.y * 128;
    const int bn = blockIdx.x * 128;

    const int lrow = tid >> 3;
    const int lkw  = (tid & 7) * 2;

    float c[4][4][4];
#pragma unroll
    for (int mi = 0; mi < 4; mi++)
#pragma unroll
        for (int ni = 0; ni < 4; ni++)
#pragma unroll
            for (int j = 0; j < 4; j++) c[mi][ni][j] = 0.0f;

    uint2 avh[4], avl[4], bvh[4], bvl[4];
#pragma unroll
    for (int r = 0; r < 4; r++) {
        size_t ra = (size_t)(bm + lrow + 32 * r) * Kw + lkw;
        size_t rb = (size_t)(bn + lrow + 32 * r) * Kw + lkw;
        avh[r] = *(const uint2*)(Ahw + ra);
        avl[r] = *(const uint2*)(Alw + ra);
        bvh[r] = *(const uint2*)(Bhw + rb);
        bvl[r] = *(const uint2*)(Blw + rb);
    }

    const int iters = K / 32;
    for (int it = 0; it < iters; it++) {
        const int st = (it & 1) * GSTAGE;

#pragma unroll
        for (int r = 0; r < 4; r++) {
            int base = st + (lrow + 32 * r) * LDTW + lkw;
            Ah[base] = avh[r].x;  Ah[base + 1] = avh[r].y;
            Al[base] = avl[r].x;  Al[base + 1] = avl[r].y;
            Bh[base] = bvh[r].x;  Bh[base + 1] = bvh[r].y;
            Bl[base] = bvl[r].x;  Bl[base + 1] = bvl[r].y;
        }
        __syncthreads();

        if (it + 1 < iters) {
            const int k16 = (it + 1) * 16;
#pragma unroll
            for (int r = 0; r < 4; r++) {
                size_t ra = (size_t)(bm + lrow + 32 * r) * Kw + k16 + lkw;
                size_t rb = (size_t)(bn + lrow + 32 * r) * Kw + k16 + lkw;
                avh[r] = *(const uint2*)(Ahw + ra);
                avl[r] = *(const uint2*)(Alw + ra);
                bvh[r] = *(const uint2*)(Bhw + rb);
                bvl[r] = *(const uint2*)(Blw + rb);
            }
        }

#pragma unroll
        for (int kk = 0; kk < 2; kk++) {
            uint32_t ahi[4][4], alo[4][4], bhi[4][2], blo[4][2];
#pragma unroll
            for (int mi = 0; mi < 4; mi++) {
                int row = warp_m * 64 + mi * 16;
                int base0 = st + (row + g)     * LDTW + kk * 8 + tig;
                int base1 = st + (row + 8 + g) * LDTW + kk * 8 + tig;
                ahi[mi][0] = Ah[base0];
                ahi[mi][1] = Ah[base1];
                ahi[mi][2] = Ah[base0 + 4];
                ahi[mi][3] = Ah[base1 + 4];
                alo[mi][0] = Al[base0];
                alo[mi][1] = Al[base1];
                alo[mi][2] = Al[base0 + 4];
                alo[mi][3] = Al[base1 + 4];
            }
#pragma unroll
            for (int ni = 0; ni < 4; ni++) {
                int col = warp_n * 32 + ni * 8;
                int base = st + (col + g) * LDTW + kk * 8 + tig;
                bhi[ni][0] = Bh[base];
                bhi[ni][1] = Bh[base + 4];
                blo[ni][0] = Bl[base];
                blo[ni][1] = Bl[base + 4];
            }
#pragma unroll
            for (int mi = 0; mi < 4; mi++)
#pragma unroll
                for (int ni = 0; ni < 4; ni++)
                    mma_bf16(c[mi][ni], ahi[mi], bhi[ni]);
#pragma unroll
            for (int mi = 0; mi < 4; mi++)
#pragma unroll
                for (int ni = 0; ni < 4; ni++)
                    mma_bf16(c[mi][ni], ahi[mi], blo[ni]);
#pragma unroll
            for (int mi = 0; mi < 4; mi++)
#pragma unroll
                for (int ni = 0; ni < 4; ni++)
                    mma_bf16(c[mi][ni], alo[mi], bhi[ni]);
        }
        __syncthreads();
    }

#pragma unroll
    for (int mi = 0; mi < 4; mi++) {
#pragma unroll
        for (int ni = 0; ni < 4; ni++) {
            int row0 = bm + warp_m * 64 + mi * 16 + g;
            int col  = bn + warp_n * 32 + ni * 8 + 2 * tig;
            *(float2*)&C[(size_t)row0 * N + col] =
                make_float2(c[mi][ni][0], c[mi][ni][1]);
            *(float2*)&C[(size_t)(row0 + 8) * N + col] =
                make_float2(c[mi][ni][2], c[mi][ni][3]);
        }
    }
}

// ---------------------------------------------------------------------------
// Per-head RMSNorm + RoPE -> fp16 outputs (UNCHANGED from R15)
// ---------------------------------------------------------------------------
__global__ void __launch_bounds__(256) rmsnorm_rope_h(const float* __restrict__ qp,
                                                      const float* __restrict__ kp,
                                                      const float* __restrict__ vp,
                                                      const float* __restrict__ freqs,
                                                      const float* __restrict__ wq,
                                                      const float* __restrict__ wk,
                                                      __half* __restrict__ qo,
                                                      __half* __restrict__ ko,
                                                      __half* __restrict__ vo)
{
    const int y = blockIdx.y;
    const int warp = threadIdx.x >> 5;
    const int lane = threadIdx.x & 31;
    const size_t row = (size_t)blockIdx.x * 8 + warp;
    const size_t bs  = row >> 4;

    if (y == 2) {
        float4 xv = *(const float4*)&vp[row * HD_ + lane * 4];
        *(uint2*)&vo[row * HD_ + lane * 4] =
            make_uint2(packhf(xv.x, xv.y), packhf(xv.z, xv.w));
        return;
    }

    const float* ptr = y ? kp : qp;
    const float* w   = y ? wk : wq;

    float4 xv = *(const float4*)&ptr[row * HD_ + lane * 4];
    float ss = xv.x * xv.x + xv.y * xv.y + xv.z * xv.z + xv.w * xv.w;
#pragma unroll
    for (int off = 16; off; off >>= 1) ss += __shfl_xor_sync(0xffffffffu, ss, off);
    float r = rsqrtf(ss * (1.0f / 128.0f) + 1e-5f);

    float4 wv = *(const float4*)&w[lane * 4];
    float nr0 = xv.x * r * wv.x;
    float ni0 = xv.y * r * wv.y;
    float nr1 = xv.z * r * wv.z;
    float ni1 = xv.w * r * wv.w;

    const float* f = freqs + bs * HD_;
    float c0 = f[2 * lane],      c1 = f[2 * lane + 1];
    float s0 = f[64 + 2 * lane], s1 = f[64 + 2 * lane + 1];

    float4 o;
    o.x = nr0 * c0 - ni0 * s0;
    o.y = nr0 * s0 + ni0 * c0;
    o.z = nr1 * c1 - ni1 * s1;
    o.w = nr1 * s1 + ni1 * c1;

    if (y == 0) {
        const float scale = 0.08838834764831845f;  // 1/sqrt(128)
        o.x *= scale; o.y *= scale; o.z *= scale; o.w *= scale;
    }
    __half* dst = y ? ko : qo;
    *(uint2*)&dst[row * HD_ + lane * 4] =
        make_uint2(packhf(o.x, o.y), packhf(o.z, o.w));
}

// ---------------------------------------------------------------------------
// fp16 flash attention, SOFTWARE-PIPELINED:
//   QKT(t+1) is issued BEFORE softmax(t) so the tensor pipe drains while the
//   ALU/MUFU softmax chain runs (and vice versa). 3-slot K/V cp.async ring.
// Br=128 q rows per CTA, Bc=64 kv per tile, 8 warps x 16 q-rows.
// Smem halfs, row stride 136: Qs[128][136], K[3][64][136], V[3][64][136]
// ---------------------------------------------------------------------------
#define QROW 136
#define FAQ  (128 * QROW)
#define FAT  (64 * QROW)
#define FA_SMEM_BYTES ((FAQ + 6 * FAT) * 2)   // 139264 B

struct FAState {
    float m[2], l[2];
    float o[16][4];
};

__device__ __forceinline__ void fa_qkt(uint32_t kb, const uint32_t (&qa)[8][4],
                                       float (&sc)[8][4], int lt, int lr)
{
#pragma unroll
    for (int nt = 0; nt < 8; nt++)
#pragma unroll
        for (int j = 0; j < 4; j++) sc[nt][j] = 0.0f;
#pragma unroll
    for (int kk = 0; kk < 8; kk++) {
#pragma unroll
        for (int ntp = 0; ntp < 4; ntp++) {
            uint32_t kbfr[4];
            uint32_t addr = kb + (uint32_t)((((2 * ntp + (lt >> 1)) * 8 + lr) * QROW
                                             + kk * 16 + (lt & 1) * 8) * 2);
            ldsm_x4(kbfr, addr);
            mma_fp16(sc[2 * ntp],     qa[kk], kbfr);
            mma_fp16(sc[2 * ntp + 1], qa[kk], kbfr + 2);
        }
    }
}

__device__ __forceinline__ void fa_softmax(float (&sc)[8][4], FAState& st)
{
#pragma unroll
    for (int rh = 0; rh < 2; rh++) {
        int i0 = rh * 2;
        float rm = -INFINITY;
#pragma unroll
        for (int nt = 0; nt < 8; nt++)
            rm = fmaxf(rm, fmaxf(sc[nt][i0], sc[nt][i0 + 1]));
        rm = fmaxf(rm, __shfl_xor_sync(0xffffffffu, rm, 1));
        rm = fmaxf(rm, __shfl_xor_sync(0xffffffffu, rm, 2));
        float mnew = fmaxf(st.m[rh], rm);
        float alpha = __expf(st.m[rh] - mnew);
        float rs = 0.0f;
#pragma unroll
        for (int nt = 0; nt < 8; nt++) {
            sc[nt][i0]     = __expf(sc[nt][i0]     - mnew);
            sc[nt][i0 + 1] = __expf(sc[nt][i0 + 1] - mnew);
            rs += sc[nt][i0] + sc[nt][i0 + 1];
        }
        rs += __shfl_xor_sync(0xffffffffu, rs, 1);
        rs += __shfl_xor_sync(0xffffffffu, rs, 2);
        st.l[rh] = st.l[rh] * alpha + rs;
        st.m[rh] = mnew;
#pragma unroll
        for (int nt = 0; nt < 16; nt++) {
            st.o[nt][i0]     *= alpha;
            st.o[nt][i0 + 1] *= alpha;
        }
    }
}

__device__ __forceinline__ void fa_pv(uint32_t vb, const float (&sc)[8][4],
                                      FAState& st, int lt, int lr)
{
#pragma unroll
    for (int kk = 0; kk < 4; kk++) {
        uint32_t a[4];
        a[0] = packhf(sc[2 * kk][0],     sc[2 * kk][1]);
        a[1] = packhf(sc[2 * kk][2],     sc[2 * kk][3]);
        a[2] = packhf(sc[2 * kk + 1][0], sc[2 * kk + 1][1]);
        a[3] = packhf(sc[2 * kk + 1][2], sc[2 * kk + 1][3]);
#pragma unroll
        for (int ntp = 0; ntp < 8; ntp++) {
            uint32_t vbfr[4];
            uint32_t addr = vb + (uint32_t)(((kk * 16 + (lt & 1) * 8 + lr) * QROW
                                             + (2 * ntp + (lt >> 1)) * 8) * 2);
            ldsm_x4_t(vbfr, addr);
            mma_fp16(st.o[2 * ntp],     a, vbfr);
            mma_fp16(st.o[2 * ntp + 1], a, vbfr + 2);
        }
    }
}

__device__ __forceinline__ void fa_load_kv(int tid, uint32_t kslot, uint32_t vslot,
                                           const __half* kh, const __half* vh,
                                           int b, int h, int kv0)
{
    for (int i = tid; i < 64 * 16; i += 256) {
        int r = i >> 4;
        int c = (i & 15) * 8;
        size_t go = (size_t)(b * S_ + kv0 + r) * D_ + h * HD_ + c;
        uint32_t soff = (uint32_t)(r * QROW + c) * 2;
        CP_ASYNC16(kslot + soff, kh + go);
        CP_ASYNC16(vslot + soff, vh + go);
    }
}

__global__ void __launch_bounds__(256, 1) flash_pipe2(const __half* __restrict__ qh,
                                                      const __half* __restrict__ kh,
                                                      const __half* __restrict__ vh,
                                                      float* __restrict__ out)
{
    extern __shared__ __half sh[];

    const int b    = blockIdx.z;
    const int h    = blockIdx.y;
    const int q0   = blockIdx.x * 128;
    const int tid  = threadIdx.x;
    const int w    = tid >> 5;
    const int lane = tid & 31;
    const int g    = lane >> 2;
    const int tig  = lane & 3;
    const int lt   = lane >> 3;
    const int lr   = lane & 7;

    const uint32_t sb  = smem_u32(sh);
    const uint32_t qb  = sb;
    uint32_t kslot[3], vslot[3];
#pragma unroll
    for (int s = 0; s < 3; s++) {
        kslot[s] = sb + (uint32_t)(FAQ + s * FAT) * 2;
        vslot[s] = sb + (uint32_t)(FAQ + (3 + s) * FAT) * 2;
    }

    // ---- group 0: Q + K/V stage 0 ----
    for (int i = tid; i < 128 * 16; i += 256) {
        int r = i >> 4;
        int c = (i & 15) * 8;
        CP_ASYNC16(qb + (uint32_t)(r * QROW + c) * 2,
                   qh + (size_t)(b * S_ + q0 + r) * D_ + h * HD_ + c);
    }
    fa_load_kv(tid, kslot[0], vslot[0], kh, vh, b, h, 0);
    CP_COMMIT();
    // ---- group 1: stage 1; group 2: stage 2 ----
    fa_load_kv(tid, kslot[1], vslot[1], kh, vh, b, h, 64);
    CP_COMMIT();
    fa_load_kv(tid, kslot[2], vslot[2], kh, vh, b, h, 128);
    CP_COMMIT();

    CP_WAIT(2);            // Q + stage0 resident
    __syncthreads();

    // ---- Hoist Q a-fragments ----
    uint32_t qa[8][4];
#pragma unroll
    for (int kk = 0; kk < 8; kk++) {
        uint32_t addr = qb + (uint32_t)(((w * 16 + (lt & 1) * 8 + lr) * QROW
                                         + kk * 16 + (lt >> 1) * 8) * 2);
        ldsm_x4(qa[kk], addr);
    }

    FAState st;
    st.m[0] = st.m[1] = -INFINITY;
    st.l[0] = st.l[1] = 0.0f;
#pragma unroll
    for (int nt = 0; nt < 16; nt++)
#pragma unroll
        for (int j = 0; j < 4; j++) st.o[nt][j] = 0.0f;

    float scA[8][4], scB[8][4];
    const int NT = S_ / 64;   // 64

    // prologue: scores of tile 0
    fa_qkt(kslot[0], qa, scA, lt, lr);

    for (int t = 0; t < NT; t += 2) {
        // ---------- body even: cur=scA, next=scB ----------
        if (t + 1 < NT) {
            CP_WAIT(1);            // stage t+1 resident (t+2 may fly)
            __syncthreads();
            fa_qkt(kslot[(t + 1) % 3], qa, scB, lt, lr);   // overlaps softmax below
        }
        fa_softmax(scA, st);
        fa_pv(vslot[t % 3], scA, st, lt, lr);
        __syncthreads();           // all warps done with slot t%3
        if (t + 3 < NT) {
            fa_load_kv(tid, kslot[t % 3], vslot[t % 3], kh, vh, b, h, (t + 3) * 64);
            CP_COMMIT();
        }
        // ---------- body odd: cur=scB, next=scA ----------
        int t1 = t + 1;
        if (t1 + 1 < NT) {
            CP_WAIT(1);
            __syncthreads();
            fa_qkt(kslot[(t1 + 1) % 3], qa, scA, lt, lr);
        }
        fa_softmax(scB, st);
        fa_pv(vslot[t1 % 3], scB, st, lt, lr);
        __syncthreads();
        if (t1 + 3 < NT) {
            fa_load_kv(tid, kslot[t1 % 3], vslot[t1 % 3], kh, vh, b, h, (t1 + 3) * 64);
            CP_COMMIT();
        }
    }

    float inv0 = 1.0f / st.l[0];
    float inv1 = 1.0f / st.l[1];
    size_t row0 = (size_t)(b * S_ + q0 + w * 16 + g);
    size_t row1 = row0 + 8;
#pragma unroll
    for (int nt = 0; nt < 16; nt++) {
        int col = h * HD_ + nt * 8 + 2 * tig;
        *(float2*)&out[row0 * D_ + col] = make_float2(st.o[nt][0] * inv0, st.o[nt][1] * inv0);
        *(float2*)&out[row1 * D_ + col] = make_float2(st.o[nt][2] * inv1, st.o[nt][3] * inv1);
    }
}

// ---------------------------------------------------------------------------
// Launch. Order chosen so launch idx 3 (0-based) = first GEMM -> ncu profile.
// ---------------------------------------------------------------------------
extern "C" void kernel_launch(void* const* d_in, const int* in_sizes, int n_in,
                              void* d_out, int out_size)
{
    const float* x     = (const float*)d_in[0];
    const float* freqs = (const float*)d_in[1];
    const float* wq    = (const float*)d_in[2];
    const float* wk    = (const float*)d_in[3];
    const float* wv    = (const float*)d_in[4];
    const float* wo    = (const float*)d_in[5];
    float* out = (float*)d_out;

    float *q, *k, *v, *ao;
    __half *qh, *kh, *vh;
    __nv_bfloat16 *xh, *xl, *aoh, *aol;
    __nv_bfloat16 *wqh, *wql, *wkh, *wkl, *wvh, *wvl, *woh, *wol;
    cudaGetSymbolAddress((void**)&q,   g_q);
    cudaGetSymbolAddress((void**)&k,   g_k);
    cudaGetSymbolAddress((void**)&v,   g_v);
    cudaGetSymbolAddress((void**)&ao,  g_ao);
    cudaGetSymbolAddress((void**)&qh,  g_qh);
    cudaGetSymbolAddress((void**)&kh,  g_kh);
    cudaGetSymbolAddress((void**)&vh,  g_vh);
    cudaGetSymbolAddress((void**)&xh,  g_xh);
    cudaGetSymbolAddress((void**)&xl,  g_xl);
    cudaGetSymbolAddress((void**)&aoh, g_aoh);
    cudaGetSymbolAddress((void**)&aol, g_aol);
    cudaGetSymbolAddress((void**)&wqh, g_wqh);
    cudaGetSymbolAddress((void**)&wql, g_wql);
    cudaGetSymbolAddress((void**)&wkh, g_wkh);
    cudaGetSymbolAddress((void**)&wkl, g_wkl);
    cudaGetSymbolAddress((void**)&wvh, g_wvh);
    cudaGetSymbolAddress((void**)&wvl, g_wvl);
    cudaGetSymbolAddress((void**)&woh, g_woh);
    cudaGetSymbolAddress((void**)&wol, g_wol);

    const int n4x = MROWS * D_ / 4;
    const int n4w = D_ * D_ / 4;

    dim3 gemm_grid(D_ / 128, MROWS / 128);  // (16, 64)
    int gsm = GEMM_SMEM_WORDS * sizeof(uint32_t);   // 81920 B
    cudaFuncSetAttribute(tbgemm3p_nt, cudaFuncAttributeMaxDynamicSharedMemorySize, gsm);
    cudaFuncSetAttribute(flash_pipe2, cudaFuncAttributeMaxDynamicSharedMemorySize,
                         FA_SMEM_BYTES);

    split_bf<<<(n4x + 255) / 256, 256>>>(x,  xh,  xl,  n4x);                       // 0
    split_bf<<<(n4w + 255) / 256, 256>>>(wq, wqh, wql, n4w);                       // 1
    split_bf<<<(n4w + 255) / 256, 256>>>(wk, wkh, wkl, n4w);                       // 2
    tbgemm3p_nt<<<gemm_grid, 256, gsm>>>(xh, xl, wqh, wql, q, MROWS, D_, D_);      // 3 <- profiled
    split_bf<<<(n4w + 255) / 256, 256>>>(wv, wvh, wvl, n4w);                       // 4
    tbgemm3p_nt<<<gemm_grid, 256, gsm>>>(xh, xl, wkh, wkl, k, MROWS, D_, D_);      // 5
    split_bf<<<(n4w + 255) / 256, 256>>>(wo, woh, wol, n4w);                       // 6
    tbgemm3p_nt<<<gemm_grid, 256, gsm>>>(xh, xl, wvh, wvl, v, MROWS, D_, D_);      // 7

    rmsnorm_rope_h<<<dim3(MROWS * H_ / 8, 3), 256>>>(
        q, k, v, freqs, (const float*)d_in[6], (const float*)d_in[7], qh, kh, vh); // 8

    flash_pipe2<<<dim3(S_ / 128, H_, B_), 256, FA_SMEM_BYTES>>>(qh, kh, vh, ao);   // 9

    split_bf<<<(n4x + 255) / 256, 256>>>(ao, aoh, aol, n4x);                       // 10
    tbgemm3p_nt<<<gemm_grid, 256, gsm>>>(aoh, aol, woh, wol, out, MROWS, D_, D_);  // 11
}

// round 17
// speedup vs baseline: 1.1457x; 1.1457x over previous
#include <cuda_runtime.h>
#include <cuda_bf16.h>
#include <cuda_fp16.h>
#include <math.h>
#include <stdint.h>

// Problem constants
#define B_  2
#define S_  4096
#define D_  2048
#define H_  16
#define HD_ 128
#define MROWS (B_ * S_)   // 8192

// Scratch in __device__ globals (allocation-guard-safe)
__device__ float g_q [(size_t)MROWS * D_];
__device__ float g_k [(size_t)MROWS * D_];
__device__ float g_v [(size_t)MROWS * D_];
__device__ float g_ao[(size_t)MROWS * D_];
__device__ __half g_qh[(size_t)MROWS * D_];
__device__ __half g_kh[(size_t)MROWS * D_];
__device__ __half g_vh[(size_t)MROWS * D_];
__device__ __nv_bfloat16 g_xh [(size_t)MROWS * D_];
__device__ __nv_bfloat16 g_xl [(size_t)MROWS * D_];
__device__ __nv_bfloat16 g_aoh[(size_t)MROWS * D_];
__device__ __nv_bfloat16 g_aol[(size_t)MROWS * D_];
__device__ __nv_bfloat16 g_wqh[(size_t)D_ * D_];
__device__ __nv_bfloat16 g_wql[(size_t)D_ * D_];
__device__ __nv_bfloat16 g_wkh[(size_t)D_ * D_];
__device__ __nv_bfloat16 g_wkl[(size_t)D_ * D_];
__device__ __nv_bfloat16 g_wvh[(size_t)D_ * D_];
__device__ __nv_bfloat16 g_wvl[(size_t)D_ * D_];
__device__ __nv_bfloat16 g_woh[(size_t)D_ * D_];
__device__ __nv_bfloat16 g_wol[(size_t)D_ * D_];

// ---------------------------------------------------------------------------
// helpers
// ---------------------------------------------------------------------------
__device__ __forceinline__ void mma_bf16(float* c, const uint32_t* a, const uint32_t* b) {
    asm volatile(
        "mma.sync.aligned.m16n8k16.row.col.f32.bf16.bf16.f32 "
        "{%0,%1,%2,%3}, {%4,%5,%6,%7}, {%8,%9}, {%0,%1,%2,%3};\n"
        : "+f"(c[0]), "+f"(c[1]), "+f"(c[2]), "+f"(c[3])
        : "r"(a[0]), "r"(a[1]), "r"(a[2]), "r"(a[3]), "r"(b[0]), "r"(b[1]));
}

__device__ __forceinline__ void mma_fp16(float* c, const uint32_t* a, const uint32_t* b) {
    asm volatile(
        "mma.sync.aligned.m16n8k16.row.col.f32.f16.f16.f32 "
        "{%0,%1,%2,%3}, {%4,%5,%6,%7}, {%8,%9}, {%0,%1,%2,%3};\n"
        : "+f"(c[0]), "+f"(c[1]), "+f"(c[2]), "+f"(c[3])
        : "r"(a[0]), "r"(a[1]), "r"(a[2]), "r"(a[3]), "r"(b[0]), "r"(b[1]));
}

__device__ __forceinline__ uint32_t packbf(float a, float b) {
    __nv_bfloat162 t = __floats2bfloat162_rn(a, b);
    return *(uint32_t*)&t;
}

__device__ __forceinline__ uint32_t packhf(float a, float b) {
    __half2 t = __floats2half2_rn(a, b);
    return *(uint32_t*)&t;
}

__device__ __forceinline__ uint32_t smem_u32(const void* p) {
    uint32_t a;
    asm("{ .reg .u64 t; cvta.to.shared.u64 t, %1; cvt.u32.u64 %0, t; }" : "=r"(a) : "l"(p));
    return a;
}

__device__ __forceinline__ void ldsm_x4(uint32_t* r, uint32_t addr) {
    asm volatile("ldmatrix.sync.aligned.m8n8.x4.shared.b16 {%0,%1,%2,%3}, [%4];"
                 : "=r"(r[0]), "=r"(r[1]), "=r"(r[2]), "=r"(r[3]) : "r"(addr));
}

__device__ __forceinline__ void ldsm_x4_t(uint32_t* r, uint32_t addr) {
    asm volatile("ldmatrix.sync.aligned.m8n8.x4.trans.shared.b16 {%0,%1,%2,%3}, [%4];"
                 : "=r"(r[0]), "=r"(r[1]), "=r"(r[2]), "=r"(r[3]) : "r"(addr));
}

#define CP_ASYNC16(dst, src) \
    asm volatile("cp.async.cg.shared.global [%0], [%1], 16;" \
                 :: "r"((uint32_t)(dst)), "l"(src) : "memory")
#define CP_COMMIT() asm volatile("cp.async.commit_group;" ::: "memory")
#define CP_WAIT(n)  asm volatile("cp.async.wait_group %0;" :: "n"(n) : "memory")

// ---------------------------------------------------------------------------
// Prep: split fp32 array into bf16 hi/lo arrays
// ---------------------------------------------------------------------------
__global__ void __launch_bounds__(256) split_bf(const float* __restrict__ in,
                                               __nv_bfloat16* __restrict__ hi,
                                               __nv_bfloat16* __restrict__ lo,
                                               int n4)
{
    int i = blockIdx.x * 256 + threadIdx.x;
    if (i >= n4) return;
    float4 v = ((const float4*)in)[i];
    float hx = __bfloat162float(__float2bfloat16(v.x));
    float hy = __bfloat162float(__float2bfloat16(v.y));
    float hz = __bfloat162float(__float2bfloat16(v.z));
    float hw = __bfloat162float(__float2bfloat16(v.w));
    ((uint2*)hi)[i] = make_uint2(packbf(hx, hy), packbf(hz, hw));
    ((uint2*)lo)[i] = make_uint2(packbf(v.x - hx, v.y - hy), packbf(v.z - hz, v.w - hw));
}

// ---------------------------------------------------------------------------
// 3-pass split-bf16 GEMM, cp.async 3-stage ring + ldmatrix fragment loads.
//   C = Ahi*Bhi + Ahi*Blo + Alo*Bhi  (fp32 accum)
// 128x128 tile, BK=32, 8 warps (2m x 4n), warp tile 64x32.
// Stage layout (halfs, row stride RSW=40 -> 80B, conflict-free cp/ldsm):
//   Ah[128][40] | Al | Bh | Bl   per stage, 3 stages.
// ---------------------------------------------------------------------------
#define RSW 40
#define GARRH (128 * RSW)                  // halfs per array = 5120
#define GSTGH (4 * GARRH)                  // halfs per stage = 20480 (40960 B)
#define GEMM_SMEM_B (3 * GSTGH * 2)        // 122880 B

__device__ __forceinline__ void gemm_load_stage(
    int tid, uint32_t stb,
    const __nv_bfloat16* __restrict__ Ahg, const __nv_bfloat16* __restrict__ Alg,
    const __nv_bfloat16* __restrict__ Bhg, const __nv_bfloat16* __restrict__ Blg,
    int bm, int bn, int k0, int K)
{
#pragma unroll
    for (int j = 0; j < 2; j++) {
        int i = tid + 256 * j;            // 0..511
        int r   = i >> 2;
        int seg = (i & 3) * 8;            // bf16 offset in row
        uint32_t d = stb + (uint32_t)(r * RSW + seg) * 2;
        size_t sa = (size_t)(bm + r) * K + k0 + seg;
        size_t sb = (size_t)(bn + r) * K + k0 + seg;
        CP_ASYNC16(d,              Ahg + sa);
        CP_ASYNC16(d + GARRH * 2,  Alg + sa);
        CP_ASYNC16(d + GARRH * 4,  Bhg + sb);
        CP_ASYNC16(d + GARRH * 6,  Blg + sb);
    }
}

__global__ void __launch_bounds__(256, 1) tbgemm3p_nt(const __nv_bfloat16* __restrict__ Ahg,
                                                      const __nv_bfloat16* __restrict__ Alg,
                                                      const __nv_bfloat16* __restrict__ Bhg,
                                                      const __nv_bfloat16* __restrict__ Blg,
                                                      float* __restrict__ C,
                                                      int M, int N, int K)
{
    extern __shared__ __half sgh[];
    const uint32_t sb = smem_u32(sgh);

    const int tid    = threadIdx.x;
    const int warp   = tid >> 5;
    const int lane   = tid & 31;
    const int warp_m = warp >> 2;      // 0..1
    const int warp_n = warp & 3;       // 0..3
    const int g      = lane >> 2;
    const int tig    = lane & 3;
    const int lt     = lane >> 3;      // ldmatrix tile idx
    const int lr     = lane & 7;

    const int bm = blockIdx.y * 128;
    const int bn = blockIdx.x * 128;

    float c[4][4][4];
#pragma unroll
    for (int mi = 0; mi < 4; mi++)
#pragma unroll
        for (int ni = 0; ni < 4; ni++)
#pragma unroll
            for (int j = 0; j < 4; j++) c[mi][ni][j] = 0.0f;

    const int iters = K / 32;   // 64

    // prologue: stages 0 and 1
    gemm_load_stage(tid, sb, Ahg, Alg, Bhg, Blg, bm, bn, 0, K);
    CP_COMMIT();
    gemm_load_stage(tid, sb + GSTGH * 2, Ahg, Alg, Bhg, Blg, bm, bn, 32, K);
    CP_COMMIT();

    for (int it = 0; it < iters; it++) {
        CP_WAIT(1);              // stage it resident (it+1 may be in flight)
        __syncthreads();         // data visible; all warps done with stage it-1

        if (it + 2 < iters) {
            gemm_load_stage(tid, sb + (uint32_t)((it + 2) % 3) * GSTGH * 2,
                            Ahg, Alg, Bhg, Blg, bm, bn, (it + 2) * 32, K);
            CP_COMMIT();
        }

        const uint32_t stb = sb + (uint32_t)(it % 3) * GSTGH * 2;
        const uint32_t Ab  = stb;
        const uint32_t Alb = stb + GARRH * 2;
        const uint32_t Bb  = stb + GARRH * 4;
        const uint32_t Blb = stb + GARRH * 6;

#pragma unroll
        for (int kk = 0; kk < 2; kk++) {
            uint32_t ahi[4][4], alo[4][4], bhi[2][4], blo[2][4];
            const int acol = kk * 16 + (lt >> 1) * 8;
            const int bcol = kk * 16 + (lt & 1) * 8;
#pragma unroll
            for (int mi = 0; mi < 4; mi++) {
                int row = warp_m * 64 + mi * 16 + (lt & 1) * 8 + lr;
                uint32_t off = (uint32_t)(row * RSW + acol) * 2;
                ldsm_x4(ahi[mi], Ab  + off);
                ldsm_x4(alo[mi], Alb + off);
            }
#pragma unroll
            for (int ntp = 0; ntp < 2; ntp++) {
                int row = warp_n * 32 + (2 * ntp + (lt >> 1)) * 8 + lr;
                uint32_t off = (uint32_t)(row * RSW + bcol) * 2;
                ldsm_x4(bhi[ntp], Bb  + off);
                ldsm_x4(blo[ntp], Blb + off);
            }
            // pass-major mma: ni = 2*ntp + e, b word pair = frag + 2*e
#pragma unroll
            for (int mi = 0; mi < 4; mi++)
#pragma unroll
                for (int ntp = 0; ntp < 2; ntp++)
#pragma unroll
                    for (int e = 0; e < 2; e++)
                        mma_bf16(c[mi][2 * ntp + e], ahi[mi], bhi[ntp] + 2 * e);
#pragma unroll
            for (int mi = 0; mi < 4; mi++)
#pragma unroll
                for (int ntp = 0; ntp < 2; ntp++)
#pragma unroll
                    for (int e = 0; e < 2; e++)
                        mma_bf16(c[mi][2 * ntp + e], ahi[mi], blo[ntp] + 2 * e);
#pragma unroll
            for (int mi = 0; mi < 4; mi++)
#pragma unroll
                for (int ntp = 0; ntp < 2; ntp++)
#pragma unroll
                    for (int e = 0; e < 2; e++)
                        mma_bf16(c[mi][2 * ntp + e], alo[mi], bhi[ntp] + 2 * e);
        }
        __syncthreads();         // all warps done reading stage it before reuse
    }

#pragma unroll
    for (int mi = 0; mi < 4; mi++) {
#pragma unroll
        for (int ni = 0; ni < 4; ni++) {
            int row0 = bm + warp_m * 64 + mi * 16 + g;
            int col  = bn + warp_n * 32 + ni * 8 + 2 * tig;
            *(float2*)&C[(size_t)row0 * N + col] =
                make_float2(c[mi][ni][0], c[mi][ni][1]);
            *(float2*)&C[(size_t)(row0 + 8) * N + col] =
                make_float2(c[mi][ni][2], c[mi][ni][3]);
        }
    }
}

// ---------------------------------------------------------------------------
// Per-head RMSNorm + RoPE -> fp16 outputs (UNCHANGED)
// ---------------------------------------------------------------------------
__global__ void __launch_bounds__(256) rmsnorm_rope_h(const float* __restrict__ qp,
                                                      const float* __restrict__ kp,
                                                      const float* __restrict__ vp,
                                                      const float* __restrict__ freqs,
                                                      const float* __restrict__ wq,
                                                      const float* __restrict__ wk,
                                                      __half* __restrict__ qo,
                                                      __half* __restrict__ ko,
                                                      __half* __restrict__ vo)
{
    const int y = blockIdx.y;
    const int warp = threadIdx.x >> 5;
    const int lane = threadIdx.x & 31;
    const size_t row = (size_t)blockIdx.x * 8 + warp;
    const size_t bs  = row >> 4;

    if (y == 2) {
        float4 xv = *(const float4*)&vp[row * HD_ + lane * 4];
        *(uint2*)&vo[row * HD_ + lane * 4] =
            make_uint2(packhf(xv.x, xv.y), packhf(xv.z, xv.w));
        return;
    }

    const float* ptr = y ? kp : qp;
    const float* w   = y ? wk : wq;

    float4 xv = *(const float4*)&ptr[row * HD_ + lane * 4];
    float ss = xv.x * xv.x + xv.y * xv.y + xv.z * xv.z + xv.w * xv.w;
#pragma unroll
    for (int off = 16; off; off >>= 1) ss += __shfl_xor_sync(0xffffffffu, ss, off);
    float r = rsqrtf(ss * (1.0f / 128.0f) + 1e-5f);

    float4 wv = *(const float4*)&w[lane * 4];
    float nr0 = xv.x * r * wv.x;
    float ni0 = xv.y * r * wv.y;
    float nr1 = xv.z * r * wv.z;
    float ni1 = xv.w * r * wv.w;

    const float* f = freqs + bs * HD_;
    float c0 = f[2 * lane],      c1 = f[2 * lane + 1];
    float s0 = f[64 + 2 * lane], s1 = f[64 + 2 * lane + 1];

    float4 o;
    o.x = nr0 * c0 - ni0 * s0;
    o.y = nr0 * s0 + ni0 * c0;
    o.z = nr1 * c1 - ni1 * s1;
    o.w = nr1 * s1 + ni1 * c1;

    if (y == 0) {
        const float scale = 0.08838834764831845f;
        o.x *= scale; o.y *= scale; o.z *= scale; o.w *= scale;
    }
    __half* dst = y ? ko : qo;
    *(uint2*)&dst[row * HD_ + lane * 4] =
        make_uint2(packhf(o.x, o.y), packhf(o.z, o.w));
}

// ---------------------------------------------------------------------------
// fp16 flash attention, software-pipelined (UNCHANGED from R16)
// ---------------------------------------------------------------------------
#define QROW 136
#define FAQ  (128 * QROW)
#define FAT  (64 * QROW)
#define FA_SMEM_BYTES ((FAQ + 6 * FAT) * 2)   // 139264 B

struct FAState {
    float m[2], l[2];
    float o[16][4];
};

__device__ __forceinline__ void fa_qkt(uint32_t kb, const uint32_t (&qa)[8][4],
                                       float (&sc)[8][4], int lt, int lr)
{
#pragma unroll
    for (int nt = 0; nt < 8; nt++)
#pragma unroll
        for (int j = 0; j < 4; j++) sc[nt][j] = 0.0f;
#pragma unroll
    for (int kk = 0; kk < 8; kk++) {
#pragma unroll
        for (int ntp = 0; ntp < 4; ntp++) {
            uint32_t kbfr[4];
            uint32_t addr = kb + (uint32_t)((((2 * ntp + (lt >> 1)) * 8 + lr) * QROW
                                             + kk * 16 + (lt & 1) * 8) * 2);
            ldsm_x4(kbfr, addr);
            mma_fp16(sc[2 * ntp],     qa[kk], kbfr);
            mma_fp16(sc[2 * ntp + 1], qa[kk], kbfr + 2);
        }
    }
}

__device__ __forceinline__ void fa_softmax(float (&sc)[8][4], FAState& st)
{
#pragma unroll
    for (int rh = 0; rh < 2; rh++) {
        int i0 = rh * 2;
        float rm = -INFINITY;
#pragma unroll
        for (int nt = 0; nt < 8; nt++)
            rm = fmaxf(rm, fmaxf(sc[nt][i0], sc[nt][i0 + 1]));
        rm = fmaxf(rm, __shfl_xor_sync(0xffffffffu, rm, 1));
        rm = fmaxf(rm, __shfl_xor_sync(0xffffffffu, rm, 2));
        float mnew = fmaxf(st.m[rh], rm);
        float alpha = __expf(st.m[rh] - mnew);
        float rs = 0.0f;
#pragma unroll
        for (int nt = 0; nt < 8; nt++) {
            sc[nt][i0]     = __expf(sc[nt][i0]     - mnew);
            sc[nt][i0 + 1] = __expf(sc[nt][i0 + 1] - mnew);
            rs += sc[nt][i0] + sc[nt][i0 + 1];
        }
        rs += __shfl_xor_sync(0xffffffffu, rs, 1);
        rs += __shfl_xor_sync(0xffffffffu, rs, 2);
        st.l[rh] = st.l[rh] * alpha + rs;
        st.m[rh] = mnew;
#pragma unroll
        for (int nt = 0; nt < 16; nt++) {
            st.o[nt][i0]     *= alpha;
            st.o[nt][i0 + 1] *= alpha;
        }
    }
}

__device__ __forceinline__ void fa_pv(uint32_t vb, const float (&sc)[8][4],
                                      FAState& st, int lt, int lr)
{
#pragma unroll
    for (int kk = 0; kk < 4; kk++) {
        uint32_t a[4];
        a[0] = packhf(sc[2 * kk][0],     sc[2 * kk][1]);
        a[1] = packhf(sc[2 * kk][2],     sc[2 * kk][3]);
        a[2] = packhf(sc[2 * kk + 1][0], sc[2 * kk + 1][1]);
        a[3] = packhf(sc[2 * kk + 1][2], sc[2 * kk + 1][3]);
#pragma unroll
        for (int ntp = 0; ntp < 8; ntp++) {
            uint32_t vbfr[4];
            uint32_t addr = vb + (uint32_t)(((kk * 16 + (lt & 1) * 8 + lr) * QROW
                                             + (2 * ntp + (lt >> 1)) * 8) * 2);
            ldsm_x4_t(vbfr, addr);
            mma_fp16(st.o[2 * ntp],     a, vbfr);
            mma_fp16(st.o[2 * ntp + 1], a, vbfr + 2);
        }
    }
}

__device__ __forceinline__ void fa_load_kv(int tid, uint32_t kslot, uint32_t vslot,
                                           const __half* kh, const __half* vh,
                                           int b, int h, int kv0)
{
    for (int i = tid; i < 64 * 16; i += 256) {
        int r = i >> 4;
        int c = (i & 15) * 8;
        size_t go = (size_t)(b * S_ + kv0 + r) * D_ + h * HD_ + c;
        uint32_t soff = (uint32_t)(r * QROW + c) * 2;
        CP_ASYNC16(kslot + soff, kh + go);
        CP_ASYNC16(vslot + soff, vh + go);
    }
}

__global__ void __launch_bounds__(256, 1) flash_pipe2(const __half* __restrict__ qh,
                                                      const __half* __restrict__ kh,
                                                      const __half* __restrict__ vh,
                                                      float* __restrict__ out)
{
    extern __shared__ __half sh[];

    const int b    = blockIdx.z;
    const int h    = blockIdx.y;
    const int q0   = blockIdx.x * 128;
    const int tid  = threadIdx.x;
    const int w    = tid >> 5;
    const int lane = tid & 31;
    const int g    = lane >> 2;
    const int tig  = lane & 3;
    const int lt   = lane >> 3;
    const int lr   = lane & 7;

    const uint32_t sb  = smem_u32(sh);
    const uint32_t qb  = sb;
    uint32_t kslot[3], vslot[3];
#pragma unroll
    for (int s = 0; s < 3; s++) {
        kslot[s] = sb + (uint32_t)(FAQ + s * FAT) * 2;
        vslot[s] = sb + (uint32_t)(FAQ + (3 + s) * FAT) * 2;
    }

    for (int i = tid; i < 128 * 16; i += 256) {
        int r = i >> 4;
        int c = (i & 15) * 8;
        CP_ASYNC16(qb + (uint32_t)(r * QROW + c) * 2,
                   qh + (size_t)(b * S_ + q0 + r) * D_ + h * HD_ + c);
    }
    fa_load_kv(tid, kslot[0], vslot[0], kh, vh, b, h, 0);
    CP_COMMIT();
    fa_load_kv(tid, kslot[1], vslot[1], kh, vh, b, h, 64);
    CP_COMMIT();
    fa_load_kv(tid, kslot[2], vslot[2], kh, vh, b, h, 128);
    CP_COMMIT();

    CP_WAIT(2);
    __syncthreads();

    uint32_t qa[8][4];
#pragma unroll
    for (int kk = 0; kk < 8; kk++) {
        uint32_t addr = qb + (uint32_t)(((w * 16 + (lt & 1) * 8 + lr) * QROW
                                         + kk * 16 + (lt >> 1) * 8) * 2);
        ldsm_x4(qa[kk], addr);
    }

    FAState st;
    st.m[0] = st.m[1] = -INFINITY;
    st.l[0] = st.l[1] = 0.0f;
#pragma unroll
    for (int nt = 0; nt < 16; nt++)
#pragma unroll
        for (int j = 0; j < 4; j++) st.o[nt][j] = 0.0f;

    float scA[8][4], scB[8][4];
    const int NT = S_ / 64;

    fa_qkt(kslot[0], qa, scA, lt, lr);

    for (int t = 0; t < NT; t += 2) {
        if (t + 1 < NT) {
            CP_WAIT(1);
            __syncthreads();
            fa_qkt(kslot[(t + 1) % 3], qa, scB, lt, lr);
        }
        fa_softmax(scA, st);
        fa_pv(vslot[t % 3], scA, st, lt, lr);
        __syncthreads();
        if (t + 3 < NT) {
            fa_load_kv(tid, kslot[t % 3], vslot[t % 3], kh, vh, b, h, (t + 3) * 64);
            CP_COMMIT();
        }
        int t1 = t + 1;
        if (t1 + 1 < NT) {
            CP_WAIT(1);
            __syncthreads();
            fa_qkt(kslot[(t1 + 1) % 3], qa, scA, lt, lr);
        }
        fa_softmax(scB, st);
        fa_pv(vslot[t1 % 3], scB, st, lt, lr);
        __syncthreads();
        if (t1 + 3 < NT) {
            fa_load_kv(tid, kslot[t1 % 3], vslot[t1 % 3], kh, vh, b, h, (t1 + 3) * 64);
            CP_COMMIT();
        }
    }

    float inv0 = 1.0f / st.l[0];
    float inv1 = 1.0f / st.l[1];
    size_t row0 = (size_t)(b * S_ + q0 + w * 16 + g);
    size_t row1 = row0 + 8;
#pragma unroll
    for (int nt = 0; nt < 16; nt++) {
        int col = h * HD_ + nt * 8 + 2 * tig;
        *(float2*)&out[row0 * D_ + col] = make_float2(st.o[nt][0] * inv0, st.o[nt][1] * inv0);
        *(float2*)&out[row1 * D_ + col] = make_float2(st.o[nt][2] * inv1, st.o[nt][3] * inv1);
    }
}

// ---------------------------------------------------------------------------
// Launch. Idx 3 (0-based) = first GEMM -> ncu profiles it.
// ---------------------------------------------------------------------------
extern "C" void kernel_launch(void* const* d_in, const int* in_sizes, int n_in,
                              void* d_out, int out_size)
{
    const float* x     = (const float*)d_in[0];
    const float* freqs = (const float*)d_in[1];
    const float* wq    = (const float*)d_in[2];
    const float* wk    = (const float*)d_in[3];
    const float* wv    = (const float*)d_in[4];
    const float* wo    = (const float*)d_in[5];
    float* out = (float*)d_out;

    float *q, *k, *v, *ao;
    __half *qh, *kh, *vh;
    __nv_bfloat16 *xh, *xl, *aoh, *aol;
    __nv_bfloat16 *wqh, *wql, *wkh, *wkl, *wvh, *wvl, *woh, *wol;
    cudaGetSymbolAddress((void**)&q,   g_q);
    cudaGetSymbolAddress((void**)&k,   g_k);
    cudaGetSymbolAddress((void**)&v,   g_v);
    cudaGetSymbolAddress((void**)&ao,  g_ao);
    cudaGetSymbolAddress((void**)&qh,  g_qh);
    cudaGetSymbolAddress((void**)&kh,  g_kh);
    cudaGetSymbolAddress((void**)&vh,  g_vh);
    cudaGetSymbolAddress((void**)&xh,  g_xh);
    cudaGetSymbolAddress((void**)&xl,  g_xl);
    cudaGetSymbolAddress((void**)&aoh, g_aoh);
    cudaGetSymbolAddress((void**)&aol, g_aol);
    cudaGetSymbolAddress((void**)&wqh, g_wqh);
    cudaGetSymbolAddress((void**)&wql, g_wql);
    cudaGetSymbolAddress((void**)&wkh, g_wkh);
    cudaGetSymbolAddress((void**)&wkl, g_wkl);
    cudaGetSymbolAddress((void**)&wvh, g_wvh);
    cudaGetSymbolAddress((void**)&wvl, g_wvl);
    cudaGetSymbolAddress((void**)&woh, g_woh);
    cudaGetSymbolAddress((void**)&wol, g_wol);

    const int n4x = MROWS * D_ / 4;
    const int n4w = D_ * D_ / 4;

    dim3 gemm_grid(D_ / 128, MROWS / 128);  // (16, 64)
    cudaFuncSetAttribute(tbgemm3p_nt, cudaFuncAttributeMaxDynamicSharedMemorySize,
                         GEMM_SMEM_B);
    cudaFuncSetAttribute(flash_pipe2, cudaFuncAttributeMaxDynamicSharedMemorySize,
                         FA_SMEM_BYTES);

    split_bf<<<(n4x + 255) / 256, 256>>>(x,  xh,  xl,  n4x);                        // 0
    split_bf<<<(n4w + 255) / 256, 256>>>(wq, wqh, wql, n4w);                        // 1
    split_bf<<<(n4w + 255) / 256, 256>>>(wk, wkh, wkl, n4w);                        // 2
    tbgemm3p_nt<<<gemm_grid, 256, GEMM_SMEM_B>>>(xh, xl, wqh, wql, q, MROWS, D_, D_); // 3 <- profiled
    split_bf<<<(n4w + 255) / 256, 256>>>(wv, wvh, wvl, n4w);                        // 4
    tbgemm3p_nt<<<gemm_grid, 256, GEMM_SMEM_B>>>(xh, xl, wkh, wkl, k, MROWS, D_, D_); // 5
    split_bf<<<(n4w + 255) / 256, 256>>>(wo, woh, wol, n4w);                        // 6
    tbgemm3p_nt<<<gemm_grid, 256, GEMM_SMEM_B>>>(xh, xl, wvh, wvl, v, MROWS, D_, D_); // 7

    rmsnorm_rope_h<<<dim3(MROWS * H_ / 8, 3), 256>>>(
        q, k, v, freqs, (const float*)d_in[6], (const float*)d_in[7], qh, kh, vh);  // 8

    flash_pipe2<<<dim3(S_ / 128, H_, B_), 256, FA_SMEM_BYTES>>>(qh, kh, vh, ao);    // 9

    split_bf<<<(n4x + 255) / 256, 256>>>(ao, aoh, aol, n4x);                        // 10
    tbgemm3p_nt<<<gemm_grid, 256, GEMM_SMEM_B>>>(aoh, aol, woh, wol, out, MROWS, D_, D_); // 11
}